// round 2
// baseline (speedup 1.0000x reference)
#include <cuda_runtime.h>
#include <cuda_bf16.h>
#include <mma.h>

using namespace nvcuda;

// Problem dims (fixed by the dataset)
constexpr int M = 8192;   // B*S = 4*2048
constexpr int N = 4096;   // D_OUT
constexpr int K = 4096;   // D_IN
constexpr int R = 16;     // LoRA rank
constexpr float SCALING = 2.0f; // 32/16

// ---- scratch (static __device__ globals; no allocation allowed) ----
__device__ __nv_bfloat16 g_xhi[(size_t)M * K];  // 64 MB
__device__ __nv_bfloat16 g_xlo[(size_t)M * K];  // 64 MB
__device__ __nv_bfloat16 g_w  [(size_t)N * K];  // 32 MB (exact bf16 of weight_int)
__device__ float         g_t  [(size_t)M * R];  // x @ A^T, fp32 exact

// ============================================================
// Prep 1: split x (fp32) into bf16 hi + lo (error ~2^-18 rel)
// ============================================================
__global__ void split_x_kernel(const float* __restrict__ x) {
    int i = blockIdx.x * blockDim.x + threadIdx.x;   // float4 index
    const int n4 = (M * K) / 4;
    if (i >= n4) return;
    float4 v = reinterpret_cast<const float4*>(x)[i];
    __nv_bfloat16 h0 = __float2bfloat16(v.x);
    __nv_bfloat16 h1 = __float2bfloat16(v.y);
    __nv_bfloat16 h2 = __float2bfloat16(v.z);
    __nv_bfloat16 h3 = __float2bfloat16(v.w);
    __nv_bfloat16 l0 = __float2bfloat16(v.x - __bfloat162float(h0));
    __nv_bfloat16 l1 = __float2bfloat16(v.y - __bfloat162float(h1));
    __nv_bfloat16 l2 = __float2bfloat16(v.z - __bfloat162float(h2));
    __nv_bfloat16 l3 = __float2bfloat16(v.w - __bfloat162float(h3));
    __nv_bfloat162* hi2 = reinterpret_cast<__nv_bfloat162*>(g_xhi);
    __nv_bfloat162* lo2 = reinterpret_cast<__nv_bfloat162*>(g_xlo);
    hi2[2 * i]     = __nv_bfloat162(h0, h1);
    hi2[2 * i + 1] = __nv_bfloat162(h2, h3);
    lo2[2 * i]     = __nv_bfloat162(l0, l1);
    lo2[2 * i + 1] = __nv_bfloat162(l2, l3);
}

// ============================================================
// Prep 2: weight_int (int32, values in [-128,127]) -> bf16 EXACT
// ============================================================
__global__ void conv_w_kernel(const int* __restrict__ w) {
    int i = blockIdx.x * blockDim.x + threadIdx.x;   // int4 index
    const int n4 = (N * K) / 4;
    if (i >= n4) return;
    int4 v = reinterpret_cast<const int4*>(w)[i];
    __nv_bfloat162* o2 = reinterpret_cast<__nv_bfloat162*>(g_w);
    o2[2 * i]     = __nv_bfloat162(__float2bfloat16((float)v.x),
                                   __float2bfloat16((float)v.y));
    o2[2 * i + 1] = __nv_bfloat162(__float2bfloat16((float)v.z),
                                   __float2bfloat16((float)v.w));
}

// ============================================================
// Prep 3: t[m, r] = sum_k x[m,k] * A[r,k]   (fp32 exact, tiny GEMM)
// Block handles 32 m-rows; A staged in smem chunks of 512 K.
// ============================================================
__global__ void lora_t_kernel(const float* __restrict__ x,
                              const float* __restrict__ A) {
    __shared__ float A_s[R * 512];   // 32 KB
    const int tid   = threadIdx.x;       // 256 threads
    const int row   = tid >> 3;          // 0..31
    const int lane8 = tid & 7;           // 0..7
    const int m     = blockIdx.x * 32 + row;

    float acc[R];
#pragma unroll
    for (int r = 0; r < R; r++) acc[r] = 0.f;

    for (int kc = 0; kc < K; kc += 512) {
        __syncthreads();
        // stage A chunk: 16 x 512 floats = 2048 float4
        for (int i = tid; i < 2048; i += 256) {
            int rr = i >> 7;        // row of A (0..15)
            int cc = i & 127;       // float4 within row
            reinterpret_cast<float4*>(A_s)[i] =
                reinterpret_cast<const float4*>(A + (size_t)rr * K + kc)[cc];
        }
        __syncthreads();
        const float* xr = x + (size_t)m * K + kc;
        for (int k = lane8 * 4; k < 512; k += 32) {
            float4 xv = *reinterpret_cast<const float4*>(xr + k);
#pragma unroll
            for (int r = 0; r < R; r++) {
                const float* Ar = A_s + r * 512 + k;
                acc[r] += xv.x * Ar[0] + xv.y * Ar[1] + xv.z * Ar[2] + xv.w * Ar[3];
            }
        }
    }
    // reduce the 8-lane groups (lanes differ only in bits 0..2 -> xor stays in group)
#pragma unroll
    for (int r = 0; r < R; r++) {
        float v = acc[r];
        v += __shfl_xor_sync(0xffffffffu, v, 1);
        v += __shfl_xor_sync(0xffffffffu, v, 2);
        v += __shfl_xor_sync(0xffffffffu, v, 4);
        if (lane8 == 0) g_t[(size_t)m * R + r] = v;
    }
}

// ============================================================
// Main GEMM: out = scale * ((x_hi + x_lo) @ W^T) + SCALING * t @ B^T
// 128x128 block tile, BK=32, 8 warps (2x4), warp tile 64x32,
// wmma m16n16k16 bf16 -> fp32.
// ============================================================
constexpr int BM = 128, BN = 128, BK = 32;
constexpr int LDA = BK + 8;   // 40 bf16: pad to dodge bank conflicts

__global__ __launch_bounds__(256, 2)
void gemm_kernel(const float* __restrict__ wscale,
                 const float* __restrict__ loraB,
                 float* __restrict__ out) {
    __shared__ float t_s[BM * R];                     // 8 KB
    __shared__ float bl_s[BN * R];                    // 8 KB
    __shared__ __align__(16) __nv_bfloat16 stage[3 * BM * LDA];  // 30 KB
    __nv_bfloat16* As_hi = stage;
    __nv_bfloat16* As_lo = stage + BM * LDA;
    __nv_bfloat16* Bs    = stage + 2 * BM * LDA;

    const int tid    = threadIdx.x;
    const int warpId = tid >> 5;
    const int lane   = tid & 31;
    const int m0 = blockIdx.y * BM;
    const int n0 = blockIdx.x * BN;
    const int wm = warpId >> 2;   // 0..1 -> m offset wm*64
    const int wn = warpId & 3;    // 0..3 -> n offset wn*32

    // preload lora operands for the epilogue (used after a later barrier)
    for (int i = tid; i < (BM * R) / 4; i += 256) {
        reinterpret_cast<float4*>(t_s)[i] =
            reinterpret_cast<const float4*>(g_t + (size_t)m0 * R)[i];
        reinterpret_cast<float4*>(bl_s)[i] =
            reinterpret_cast<const float4*>(loraB + (size_t)n0 * R)[i];
    }

    wmma::fragment<wmma::accumulator, 16, 16, 16, float> acc[4][2];
#pragma unroll
    for (int i = 0; i < 4; i++)
#pragma unroll
        for (int j = 0; j < 2; j++) wmma::fill_fragment(acc[i][j], 0.f);

    for (int kt = 0; kt < K; kt += BK) {
        __syncthreads();
        // stage A_hi, A_lo, B: each 128 rows x 32 bf16 = 512 uint4
        for (int i = tid; i < 512; i += 256) {
            int row = i >> 2;
            int col = (i & 3) * 8;
            size_t gA = (size_t)(m0 + row) * K + kt + col;
            size_t gB = (size_t)(n0 + row) * K + kt + col;
            *reinterpret_cast<uint4*>(As_hi + row * LDA + col) =
                *reinterpret_cast<const uint4*>(g_xhi + gA);
            *reinterpret_cast<uint4*>(As_lo + row * LDA + col) =
                *reinterpret_cast<const uint4*>(g_xlo + gA);
            *reinterpret_cast<uint4*>(Bs + row * LDA + col) =
                *reinterpret_cast<const uint4*>(g_w + gB);
        }
        __syncthreads();
#pragma unroll
        for (int kk = 0; kk < BK; kk += 16) {
            wmma::fragment<wmma::matrix_a, 16, 16, 16, __nv_bfloat16, wmma::row_major> ah[4], al[4];
            wmma::fragment<wmma::matrix_b, 16, 16, 16, __nv_bfloat16, wmma::col_major> bf[2];
#pragma unroll
            for (int i = 0; i < 4; i++) {
                wmma::load_matrix_sync(ah[i], As_hi + (wm * 64 + i * 16) * LDA + kk, LDA);
                wmma::load_matrix_sync(al[i], As_lo + (wm * 64 + i * 16) * LDA + kk, LDA);
            }
#pragma unroll
            for (int j = 0; j < 2; j++)
                wmma::load_matrix_sync(bf[j], Bs + (wn * 32 + j * 16) * LDA + kk, LDA);
#pragma unroll
            for (int i = 0; i < 4; i++)
#pragma unroll
                for (int j = 0; j < 2; j++) {
                    wmma::mma_sync(acc[i][j], ah[i], bf[j], acc[i][j]);
                    wmma::mma_sync(acc[i][j], al[i], bf[j], acc[i][j]);
                }
        }
    }

    __syncthreads();   // staging smem now reusable as epilogue patches
    const float scale = wscale[0];
    // per-warp 16x20 fp32 patch inside `stage` (5120 B apart, 16B aligned)
    float* patch = reinterpret_cast<float*>(stage) + warpId * 16 * 20;

#pragma unroll
    for (int i = 0; i < 4; i++) {
#pragma unroll
        for (int j = 0; j < 2; j++) {
            wmma::store_matrix_sync(patch, acc[i][j], 20, wmma::mem_row_major);
            __syncwarp();
#pragma unroll
            for (int e = 0; e < 8; e++) {
                int idx = lane * 8 + e;        // 0..255
                int r = idx >> 4, c = idx & 15;
                int lm = wm * 64 + i * 16 + r;
                int ln = wn * 32 + j * 16 + c;
                float v = scale * patch[r * 20 + c];
                const float* tp = t_s + lm * R;
                const float* bp = bl_s + ln * R;
                float d = 0.f;
#pragma unroll
                for (int rr = 0; rr < R; rr++) d += tp[rr] * bp[rr];
                out[(size_t)(m0 + lm) * N + (n0 + ln)] = v + SCALING * d;
            }
            __syncwarp();
        }
    }
}

// ============================================================
// launch
// ============================================================
extern "C" void kernel_launch(void* const* d_in, const int* in_sizes, int n_in,
                              void* d_out, int out_size) {
    const float* x  = (const float*)d_in[0];   // [4,2048,4096] f32
    const int*   wq = (const int*)d_in[1];     // [4096,4096] int32
    const float* ws = (const float*)d_in[2];   // [1] f32
    const float* lA = (const float*)d_in[3];   // [16,4096] f32
    const float* lB = (const float*)d_in[4];   // [4096,16] f32
    float* out = (float*)d_out;                // [4,2048,4096] f32

    split_x_kernel<<<(M * K / 4 + 255) / 256, 256>>>(x);
    conv_w_kernel<<<(N * K / 4 + 255) / 256, 256>>>(wq);
    lora_t_kernel<<<M / 32, 256>>>(x, lA);

    dim3 grid(N / BN, M / BM);   // 32 x 64
    gemm_kernel<<<grid, 256>>>(ws, lB, out);
}